// round 8
// baseline (speedup 1.0000x reference)
#include <cuda_runtime.h>
#include <cuda_bf16.h>
#include <cstdint>

// ---------------- problem constants ----------------
#define N_IN   200000
#define N_OUT  100000
#define NE     1600000
#define CIN    64
#define CO     128
#define KHALF  576
#define MTILE  128
#define MPAD   100096          // 782 * 128
#define NTILES 782
#define KCH    32              // K elems per pipeline chunk
#define NCHUNK 18              // 576 / 32
#define SLOT   32768           // 4 A-arrays x [128][32] bf16 (8KB each)
#define NSTEPS 36              // 576 / 16 k16-steps
#define SIMP_OFF (3 * SLOT)    // smem offset of s_imp[128]

#define ASZ    ((size_t)MPAD * KHALF)

// ---------------- device scratch (no allocs allowed) ----------------
__device__ int            g_offs[N_OUT + 1];
// A arrays: 0=Auh 1=Aul 2=Awh 3=Awl ; padded rows stay zero (.bss)
__device__ __nv_bfloat16  g_A[4][ASZ];
// B pre-packed in mma fragment order: [arr(h/l)][k16-step][w_n][lane][8]
__device__ uint32_t       g_Bp[2 * NSTEPS * 4 * 32 * 8];

// ---------------- helpers ----------------
__device__ __forceinline__ uint32_t smem_u32(const void* p) {
    uint32_t a;
    asm("{ .reg .u64 t; cvta.to.shared.u64 t, %1; cvt.u32.u64 %0, t; }"
        : "=r"(a) : "l"(p));
    return a;
}
__device__ __forceinline__ uint32_t sw64(uint32_t o) {   // 64B-row swizzle
    return o ^ ((o >> 3) & 0x30);
}
__device__ __forceinline__ void cp16(uint32_t dst, const void* src) {
    asm volatile("cp.async.cg.shared.global [%0], [%1], 16;" :: "r"(dst), "l"(src));
}
#define CP_COMMIT asm volatile("cp.async.commit_group;" ::: "memory")

__device__ __forceinline__ void ldm4(uint32_t& r0, uint32_t& r1,
                                     uint32_t& r2, uint32_t& r3, uint32_t a) {
    asm volatile("ldmatrix.sync.aligned.m8n8.x4.shared.b16 {%0,%1,%2,%3}, [%4];"
                 : "=r"(r0), "=r"(r1), "=r"(r2), "=r"(r3) : "r"(a));
}
__device__ __forceinline__ void mma_bf16(float* c, const uint32_t* a,
                                         uint32_t b0, uint32_t b1) {
    asm volatile(
        "mma.sync.aligned.m16n8k16.row.col.f32.bf16.bf16.f32 "
        "{%0,%1,%2,%3}, {%4,%5,%6,%7}, {%8,%9}, {%0,%1,%2,%3};"
        : "+f"(c[0]), "+f"(c[1]), "+f"(c[2]), "+f"(c[3])
        : "r"(a[0]), "r"(a[1]), "r"(a[2]), "r"(a[3]), "r"(b0), "r"(b1));
}

// ---------------------------------------------------------------------------
// Kernel 1: CSR offsets via adjacent-diff over sorted neighbors_out_index
// ---------------------------------------------------------------------------
__global__ void build_offsets_kernel(const int* __restrict__ out_idx) {
    int e = blockIdx.x * blockDim.x + threadIdx.x;
    if (e >= NE) return;
    int b = __ldg(out_idx + e);
    int a = (e == 0) ? -1 : __ldg(out_idx + e - 1);
    for (int n = a + 1; n <= b; n++) g_offs[n] = e;
    if (e == NE - 1)
        for (int n = b + 1; n <= N_OUT; n++) g_offs[n] = NE;
}

// ---------------------------------------------------------------------------
// Kernel 2: pack weights straight into mma-fragment order, bf16 hi/lo.
//   col = wn*32 + nf*8 + (lane>>2) ;  k = s*16 + (lane&3)*2 + r*8
// ---------------------------------------------------------------------------
__global__ void build_bp_kernel(const float* __restrict__ Wa,
                                const float* __restrict__ Wb) {
    int i = blockIdx.x * blockDim.x + threadIdx.x;
    if (i >= 2 * NSTEPS * 4 * 32 * 8) return;
    const int arr  = i / (NSTEPS * 1024);
    const int rem  = i % (NSTEPS * 1024);
    const int s    = rem / 1024;
    const int wn   = (rem % 1024) / 256;
    const int lane = (rem % 256) / 8;
    const int j    = rem % 8;
    const int nf = j >> 1, r = j & 1;
    const int col = wn * 32 + nf * 8 + (lane >> 2);
    const int k   = s * 16 + (lane & 3) * 2 + r * 8;
    float v0, v1;
    if (col < 96) { v0 = __ldg(Wa + k * 96 + col); v1 = __ldg(Wa + (k + 1) * 96 + col); }
    else          { v0 = __ldg(Wb + k * 32 + col - 96); v1 = __ldg(Wb + (k + 1) * 32 + col - 96); }
    __nv_bfloat16 h0 = __float2bfloat16(v0);
    __nv_bfloat16 h1 = __float2bfloat16(v1);
    __nv_bfloat16 x0 = h0, x1 = h1;
    if (arr == 1) {
        x0 = __float2bfloat16(v0 - __bfloat162float(h0));
        x1 = __float2bfloat16(v1 - __bfloat162float(h1));
    }
    g_Bp[i] = ((uint32_t)__bfloat16_as_ushort(x1) << 16) | __bfloat16_as_ushort(x0);
}

// ---------------------------------------------------------------------------
// FUSED kernel: one CTA per 128-point tile.
// Phase 1: 8 warps x 16 points — bin into smem, write hi/lo bf16 staging for
//          THIS tile's rows (stays L2-hot), imp_sum into smem.
// Phase 2: round-7 GEMM on those rows (A via 3-stage cp.async; B via
//          register-double-buffered LDG of pre-packed fragments).
// smem: stages [0, 3*SLOT) overlaid with phase-1 bins [0, 36864); s_imp after.
// ---------------------------------------------------------------------------
extern __shared__ __align__(128) char gsm[];

__global__ __launch_bounds__(256, 2)
void fused_kernel(const float* __restrict__ feats,
                  const float* __restrict__ importance,
                  const float* __restrict__ b_a,
                  const float* __restrict__ b_b,
                  const int*   __restrict__ nbr,
                  const int*   __restrict__ kid,
                  float*       __restrict__ out) {
    const int tid  = threadIdx.x, lane = tid & 31, wid = tid >> 5;
    const size_t mtile = (size_t)blockIdx.x * MTILE;
    float* s_imp = reinterpret_cast<float*>(gsm + SIMP_OFF);

    // ================= Phase 1: binning =================
    {
        float*  b  = reinterpret_cast<float*>(gsm) + wid * 1152;
        float2* b2 = reinterpret_cast<float2*>(b);
        float4* bz = reinterpret_cast<float4*>(b);

        for (int pi = 0; pi < 16; pi++) {
            const int n = (int)mtile + wid * 16 + pi;
            if (n >= N_OUT) break;      // padding rows: g_A stays .bss zero

            #pragma unroll
            for (int i = lane; i < 1152 / 4; i += 32)
                bz[i] = make_float4(0.f, 0.f, 0.f, 0.f);
            __syncwarp();

            const int e0 = g_offs[n], e1 = g_offs[n + 1];
            float impacc = 0.f;
            #pragma unroll 2
            for (int e = e0; e < e1; e++) {
                const int    src = __ldg(nbr + e);
                const int    k   = __ldg(kid + e);
                const float  im  = __ldg(importance + src);
                const float2 f   = *reinterpret_cast<const float2*>(
                                       feats + (size_t)src * CIN + 2 * lane);
                const int o2 = k * 32 + lane;
                float2 bu = b2[o2];
                bu.x += f.x; bu.y += f.y;
                b2[o2] = bu;
                float2 bw = b2[288 + o2];
                bw.x = fmaf(f.x, im, bw.x); bw.y = fmaf(f.y, im, bw.y);
                b2[288 + o2] = bw;
                impacc += im;
            }
            __syncwarp();

            const size_t base = (size_t)n * KHALF;
            #pragma unroll
            for (int j = 0; j < KHALF; j += 64) {
                const int kc = j + 2 * lane;
                {   // u half -> g_A[0]/g_A[1]
                    float2 v = *reinterpret_cast<float2*>(b + kc);
                    __nv_bfloat162 hh, ll;
                    hh.x = __float2bfloat16(v.x); hh.y = __float2bfloat16(v.y);
                    ll.x = __float2bfloat16(v.x - __bfloat162float(hh.x));
                    ll.y = __float2bfloat16(v.y - __bfloat162float(hh.y));
                    *reinterpret_cast<uint32_t*>(&g_A[0][base + kc]) =
                        *reinterpret_cast<uint32_t*>(&hh);
                    *reinterpret_cast<uint32_t*>(&g_A[1][base + kc]) =
                        *reinterpret_cast<uint32_t*>(&ll);
                }
                {   // w half -> g_A[2]/g_A[3]
                    float2 v = *reinterpret_cast<float2*>(b + 576 + kc);
                    __nv_bfloat162 hh, ll;
                    hh.x = __float2bfloat16(v.x); hh.y = __float2bfloat16(v.y);
                    ll.x = __float2bfloat16(v.x - __bfloat162float(hh.x));
                    ll.y = __float2bfloat16(v.y - __bfloat162float(hh.y));
                    *reinterpret_cast<uint32_t*>(&g_A[2][base + kc]) =
                        *reinterpret_cast<uint32_t*>(&hh);
                    *reinterpret_cast<uint32_t*>(&g_A[3][base + kc]) =
                        *reinterpret_cast<uint32_t*>(&ll);
                }
            }
            if (lane == 0) {
                s_imp[wid * 16 + pi] = impacc;
                out[(size_t)N_OUT * CO + n] = impacc;   // imp_sum output
            }
        }
    }
    __syncthreads();

    // ================= Phase 2: GEMM =================
    const int w_m = wid & 1, w_n = wid >> 1;
    const int g = lane >> 2, tig = lane & 3;
    const uint32_t sbase = smem_u32(gsm);

    // cp.async geometry: 2 x 16B per thread per A array (128 rows x 4 cols)
    int   aIdx[2];
    uint32_t dOff[2];
    #pragma unroll
    for (int q = 0; q < 2; q++) {
        const int idx = q * 256 + tid;      // 0..511
        const int row = idx >> 2, c = idx & 3;
        aIdx[q] = (int)((mtile + row) * KHALF + c * 8);
        dOff[q] = sw64(row * 64 + c * 16);
    }

    const uint32_t aOffB = (uint32_t)(w_m * 64 + (lane & 15)) * 64
                         + ((lane >> 4) & 1) * 16;
    const uint32_t ahSel = (w_n < 3) ? 0u : 16384u;   // Auh vs Awh

    const uint32_t* bpH = g_Bp + w_n * 256 + lane * 8;
    const uint32_t* bpL = bpH + NSTEPS * 4 * 256;

    float acc[4][4][4];
    #pragma unroll
    for (int i = 0; i < 4; i++)
        #pragma unroll
        for (int j = 0; j < 4; j++)
            #pragma unroll
            for (int q = 0; q < 4; q++) acc[i][j][q] = 0.f;

    auto issue = [&](int c) {
        const uint32_t st = sbase + (uint32_t)(c % 3) * SLOT;
        const int k0 = c * KCH;
        #pragma unroll
        for (int q = 0; q < 2; q++)
            #pragma unroll
            for (int arr = 0; arr < 4; arr++)
                cp16(st + arr * 8192 + dOff[q], &g_A[arr][0] + aIdx[q] + k0);
        CP_COMMIT;
    };

    uint32_t breg[2][16];
    auto loadB = [&](int s, uint32_t* d) {
        const uint32_t* ph = bpH + (size_t)s * 1024;
        const uint32_t* pl = bpL + (size_t)s * 1024;
        *reinterpret_cast<uint4*>(d)      = __ldg(reinterpret_cast<const uint4*>(ph));
        *reinterpret_cast<uint4*>(d + 4)  = __ldg(reinterpret_cast<const uint4*>(ph + 4));
        *reinterpret_cast<uint4*>(d + 8)  = __ldg(reinterpret_cast<const uint4*>(pl));
        *reinterpret_cast<uint4*>(d + 12) = __ldg(reinterpret_cast<const uint4*>(pl + 4));
    };

    issue(0); issue(1);
    loadB(0, breg[0]);

    for (int c = 0; c < NCHUNK; c++) {
        if (c + 1 < NCHUNK) asm volatile("cp.async.wait_group 1;" ::: "memory");
        else                asm volatile("cp.async.wait_group 0;" ::: "memory");
        __syncthreads();
        if (c + 2 < NCHUNK) issue(c + 2);

        const uint32_t st  = sbase + (uint32_t)(c % 3) * SLOT;
        const uint32_t sAh = st + ahSel;
        const uint32_t sAl = sAh + 8192;

        #pragma unroll
        for (int ks = 0; ks < 2; ks++) {
            const int s = 2 * c + ks;
            if (s + 1 < 2 * NCHUNK) loadB(s + 1, breg[ks ^ 1]);
            const uint32_t* bh = breg[ks];
            const uint32_t* bl = breg[ks] + 8;
            #pragma unroll
            for (int mf = 0; mf < 4; mf++) {
                const uint32_t ao = sw64(aOffB + mf * 1024 + ks * 32);
                uint32_t ah[4], al[4];
                ldm4(ah[0], ah[1], ah[2], ah[3], sAh + ao);
                ldm4(al[0], al[1], al[2], al[3], sAl + ao);
                #pragma unroll
                for (int nf = 0; nf < 4; nf++) {
                    mma_bf16(acc[mf][nf], ah, bh[2 * nf], bh[2 * nf + 1]);
                    mma_bf16(acc[mf][nf], ah, bl[2 * nf], bl[2 * nf + 1]);
                    mma_bf16(acc[mf][nf], al, bh[2 * nf], bh[2 * nf + 1]);
                }
            }
        }
    }

    // ---- epilogue: bias / normalize / relu / store ----
    float bias[4][2];
    #pragma unroll
    for (int nf = 0; nf < 4; nf++) {
        const int col = w_n * 32 + nf * 8 + 2 * tig;
        bias[nf][0] = (col < 96) ? __ldg(b_a + col)     : __ldg(b_b + col - 96);
        bias[nf][1] = (col < 96) ? __ldg(b_a + col + 1) : __ldg(b_b + col - 95);
    }

    #pragma unroll
    for (int mf = 0; mf < 4; mf++) {
        #pragma unroll
        for (int half = 0; half < 2; half++) {
            const int m = w_m * 64 + mf * 16 + g + half * 8;
            const int n = (int)mtile + m;
            if (n >= N_OUT) continue;
            float inv = 1.f;
            if (w_n == 3) inv = 1.f / fmaxf(s_imp[m], 1e-8f);
            #pragma unroll
            for (int nf = 0; nf < 4; nf++) {
                const int col = w_n * 32 + nf * 8 + 2 * tig;
                float2 r;
                r.x = fmaxf(fmaf(acc[mf][nf][half * 2 + 0], inv, bias[nf][0]), 0.f);
                r.y = fmaxf(fmaf(acc[mf][nf][half * 2 + 1], inv, bias[nf][1]), 0.f);
                *reinterpret_cast<float2*>(out + (size_t)n * CO + col) = r;
            }
        }
    }
}

// ---------------------------------------------------------------------------
extern "C" void kernel_launch(void* const* d_in, const int* in_sizes, int n_in,
                              void* d_out, int out_size) {
    const float* feats      = (const float*)d_in[0];
    const float* importance = (const float*)d_in[1];
    const float* W_a        = (const float*)d_in[2];
    const float* b_a        = (const float*)d_in[3];
    const float* W_b        = (const float*)d_in[4];
    const float* b_b        = (const float*)d_in[5];
    const int*   nbr        = (const int*)d_in[6];
    const int*   kid        = (const int*)d_in[7];
    const int*   oid        = (const int*)d_in[8];
    float*       out        = (float*)d_out;

    build_offsets_kernel<<<(NE + 255) / 256, 256>>>(oid);
    build_bp_kernel<<<(2 * NSTEPS * 4 * 32 * 8 + 255) / 256, 256>>>(W_a, W_b);

    const int smem_bytes = 3 * SLOT + 512;   // 98,816 B
    cudaFuncSetAttribute(fused_kernel,
                         cudaFuncAttributeMaxDynamicSharedMemorySize, smem_bytes);
    fused_kernel<<<NTILES, 256, smem_bytes>>>(
        feats, importance, b_a, b_b, nbr, kid, out);
}

// round 9
// speedup vs baseline: 1.1669x; 1.1669x over previous
#include <cuda_runtime.h>
#include <cuda_bf16.h>
#include <cstdint>

// ---------------- problem constants ----------------
#define N_IN   200000
#define N_OUT  100000
#define NE     1600000
#define CIN    64
#define CO     128
#define KHALF  576
#define MTILE  128
#define MPAD   100096          // 782 * 128
#define NTILES 782
#define KCH    32              // K elems per pipeline chunk
#define NCHUNK 18              // 576 / 32

#define ASZ    ((size_t)MPAD * KHALF)
#define BSZ    ((size_t)CO * KHALF)

// ---------------- device scratch (no allocs allowed) ----------------
__device__ int            g_offs[N_OUT + 1];
__device__ float          g_imp[N_OUT];
__device__ int2           g_edges[NE];             // {src<<4|k, imp bits}
// A arrays: 0=Auh 1=Aul 2=Awh 3=Awl ; padded rows stay zero (.bss)
__device__ __nv_bfloat16  g_A[4][ASZ];
// B arrays: 0=Bh 1=Bl  (row-major [o][k])
__device__ __nv_bfloat16  g_B[2][BSZ];

// ---------------- helpers ----------------
__device__ __forceinline__ uint32_t smem_u32(const void* p) {
    uint32_t a;
    asm("{ .reg .u64 t; cvta.to.shared.u64 t, %1; cvt.u32.u64 %0, t; }"
        : "=r"(a) : "l"(p));
    return a;
}
__device__ __forceinline__ uint32_t sw64(uint32_t o) {   // 64B-row swizzle
    return o ^ ((o >> 3) & 0x30);
}
__device__ __forceinline__ void cp16(uint32_t dst, const void* src) {
    asm volatile("cp.async.cg.shared.global [%0], [%1], 16;" :: "r"(dst), "l"(src));
}
#define CP_COMMIT asm volatile("cp.async.commit_group;" ::: "memory")

__device__ __forceinline__ void ldm4(uint32_t& r0, uint32_t& r1,
                                     uint32_t& r2, uint32_t& r3, uint32_t a) {
    asm volatile("ldmatrix.sync.aligned.m8n8.x4.shared.b16 {%0,%1,%2,%3}, [%4];"
                 : "=r"(r0), "=r"(r1), "=r"(r2), "=r"(r3) : "r"(a));
}
__device__ __forceinline__ void mma_bf16(float* c, const uint32_t* a,
                                         uint32_t b0, uint32_t b1) {
    asm volatile(
        "mma.sync.aligned.m16n8k16.row.col.f32.bf16.bf16.f32 "
        "{%0,%1,%2,%3}, {%4,%5,%6,%7}, {%8,%9}, {%0,%1,%2,%3};"
        : "+f"(c[0]), "+f"(c[1]), "+f"(c[2]), "+f"(c[3])
        : "r"(a[0]), "r"(a[1]), "r"(a[2]), "r"(a[3]), "r"(b0), "r"(b1));
}

// ---------------------------------------------------------------------------
// Kernel 1: CSR offsets via adjacent-diff over sorted neighbors_out_index
// ---------------------------------------------------------------------------
__global__ void build_offsets_kernel(const int* __restrict__ out_idx) {
    int e = blockIdx.x * blockDim.x + threadIdx.x;
    if (e >= NE) return;
    int b = __ldg(out_idx + e);
    int a = (e == 0) ? -1 : __ldg(out_idx + e - 1);
    for (int n = a + 1; n <= b; n++) g_offs[n] = e;
    if (e == NE - 1)
        for (int n = b + 1; n <= N_OUT; n++) g_offs[n] = NE;
}

// ---------------------------------------------------------------------------
// Kernel 1b: pack per-edge records {src<<4 | k, importance[src]}
// ---------------------------------------------------------------------------
__global__ void pack_edges_kernel(const int* __restrict__ nbr,
                                  const int* __restrict__ kid,
                                  const float* __restrict__ importance) {
    int e = blockIdx.x * blockDim.x + threadIdx.x;
    if (e >= NE) return;
    const int src = __ldg(nbr + e);
    const int k   = __ldg(kid + e);
    int2 r;
    r.x = (src << 4) | k;
    r.y = __float_as_int(__ldg(importance + src));
    g_edges[e] = r;
}

// ---------------------------------------------------------------------------
// Kernel 2: compressed weights [128][576] bf16 hi/lo
// ---------------------------------------------------------------------------
__global__ void build_w_kernel(const float* __restrict__ Wa,
                               const float* __restrict__ Wb) {
    int i = blockIdx.x * blockDim.x + threadIdx.x;
    if (i >= CO * KHALF) return;
    int o = i / KHALF, k = i % KHALF;
    float v = (o < 96) ? __ldg(Wa + k * 96 + o) : __ldg(Wb + k * 32 + (o - 96));
    __nv_bfloat16 h = __float2bfloat16(v);
    g_B[0][i] = h;
    g_B[1][i] = __float2bfloat16(v - __bfloat162float(h));
}

// ---------------------------------------------------------------------------
// Kernel 3: binning. One warp per output point; fp32 bins in smem.
// Packed edge records (1 uniform LDG.64/edge), wide LDS.128/STG.64 writeout.
// ---------------------------------------------------------------------------
__global__ __launch_bounds__(256)
void bin_kernel(const float* __restrict__ feats,
                float*       __restrict__ out) {
    __shared__ float sb[8][1152];
    const int lane = threadIdx.x & 31;
    const int w    = threadIdx.x >> 5;
    const int n    = blockIdx.x * 8 + w;

    float*  b  = sb[w];
    float2* b2 = reinterpret_cast<float2*>(b);
    float4* bz = reinterpret_cast<float4*>(b);
    #pragma unroll
    for (int i = lane; i < 1152 / 4; i += 32) bz[i] = make_float4(0.f, 0.f, 0.f, 0.f);
    __syncwarp();

    const int e0 = g_offs[n], e1 = g_offs[n + 1];
    float impacc = 0.f;
    #pragma unroll 4
    for (int e = e0; e < e1; e++) {
        const int2  rec = __ldg(g_edges + e);
        const int   src = rec.x >> 4;
        const int   k   = rec.x & 15;
        const float im  = __int_as_float(rec.y);
        const float2 f  = *reinterpret_cast<const float2*>(
                              feats + (size_t)src * CIN + 2 * lane);
        const int o2 = k * 32 + lane;
        float2 bu = b2[o2];
        bu.x += f.x; bu.y += f.y;
        b2[o2] = bu;
        float2 bw = b2[288 + o2];
        bw.x = fmaf(f.x, im, bw.x); bw.y = fmaf(f.y, im, bw.y);
        b2[288 + o2] = bw;
        impacc += im;
    }
    __syncwarp();

    // writeout: lane owns 4 consecutive elements per iteration.
    // m in [0,1152): m<576 -> u (arrays 0/1, col=m), else w (arrays 2/3, col=m-576)
    const size_t rb = (size_t)n * KHALF;
    #pragma unroll
    for (int it = 0; it < 9; it++) {
        const int m = it * 128 + lane * 4;
        const float4 v = *reinterpret_cast<const float4*>(b + m);
        const bool isU = m < 576;
        const int col  = isU ? m : m - 576;
        __nv_bfloat16* aH = isU ? g_A[0] : g_A[2];
        __nv_bfloat16* aL = isU ? g_A[1] : g_A[3];
        __nv_bfloat162 h01, h23, l01, l23;
        h01.x = __float2bfloat16(v.x); h01.y = __float2bfloat16(v.y);
        h23.x = __float2bfloat16(v.z); h23.y = __float2bfloat16(v.w);
        l01.x = __float2bfloat16(v.x - __bfloat162float(h01.x));
        l01.y = __float2bfloat16(v.y - __bfloat162float(h01.y));
        l23.x = __float2bfloat16(v.z - __bfloat162float(h23.x));
        l23.y = __float2bfloat16(v.w - __bfloat162float(h23.y));
        uint2 hv, lv;
        hv.x = *reinterpret_cast<uint32_t*>(&h01);
        hv.y = *reinterpret_cast<uint32_t*>(&h23);
        lv.x = *reinterpret_cast<uint32_t*>(&l01);
        lv.y = *reinterpret_cast<uint32_t*>(&l23);
        *reinterpret_cast<uint2*>(aH + rb + col) = hv;
        *reinterpret_cast<uint2*>(aL + rb + col) = lv;
    }
    if (lane == 0) {
        g_imp[n] = impacc;
        out[(size_t)N_OUT * CO + n] = impacc;   // imp_sum output
    }
}

// ---------------------------------------------------------------------------
// Kernel 4: HMMA GEMM — round-4 verbatim (fastest measured: 151 us).
// Stage (48KB): [Auh 8K][Aul 8K][Awh 8K][Awl 8K][Bh 8K][Bl 8K], 64B rows sw64.
// 3 stages (147KB -> 1 CTA/SM). Warps: 2(M64) x 4(N32); w_n<3->Au, w_n==3->Aw.
// ---------------------------------------------------------------------------
#define STAGE  49152
extern __shared__ char gsm[];

__device__ __forceinline__ void stage_loads(uint32_t st, size_t mtile, int c, int tid) {
    const int k0 = c * KCH;
    const int row = tid >> 1, cc = tid & 1;
    const int aIdx = (int)((mtile + row) * KHALF + cc * 8 + k0);
    const int bIdx = row * KHALF + cc * 8 + k0;
    const uint32_t dOff = sw64((uint32_t)(row * 64 + cc * 16));
    // wait — 256 threads cover 128 rows x 2 cols of 8 elems = 16 elems/row; need 32.
    // Use two passes: cols {cc, cc+2}
    #pragma unroll
    for (int p = 0; p < 2; p++) {
        const int c4 = cc + p * 2;
        const uint32_t d = sw64((uint32_t)(row * 64 + c4 * 16));
        const int ai = (int)((mtile + row) * KHALF + c4 * 8 + k0);
        const int bi = row * KHALF + c4 * 8 + k0;
        #pragma unroll
        for (int arr = 0; arr < 4; arr++)
            cp16(st + arr * 8192 + d, &g_A[arr][0] + ai);
        #pragma unroll
        for (int arr = 0; arr < 2; arr++)
            cp16(st + 32768 + arr * 8192 + d, &g_B[arr][0] + bi);
    }
    (void)aIdx; (void)bIdx; (void)dOff;
    CP_COMMIT;
}

__global__ __launch_bounds__(256, 1)
void gemm_kernel(const float* __restrict__ b_a,
                 const float* __restrict__ b_b,
                 float*       __restrict__ out) {
    const int tid = threadIdx.x, lane = tid & 31, wid = tid >> 5;
    const int w_m = wid & 1, w_n = wid >> 1;
    const int g = lane >> 2, tig = lane & 3;
    const size_t mtile = (size_t)blockIdx.x * MTILE;
    const uint32_t sbase = smem_u32(gsm);

    // ldmatrix per-lane base offsets, 64B rows
    const uint32_t aOffB = (uint32_t)(w_m * 64 + (lane & 15)) * 64
                         + ((lane >> 4) & 1) * 16;
    const uint32_t bOffB = (uint32_t)(w_n * 32 + (lane & 7) + ((lane >> 4) & 1) * 8) * 64
                         + ((lane >> 3) & 1) * 16;
    const uint32_t ahSel = (w_n < 3) ? 0u : 16384u;   // Auh vs Awh

    float acc[4][4][4];
    #pragma unroll
    for (int i = 0; i < 4; i++)
        #pragma unroll
        for (int j = 0; j < 4; j++)
            #pragma unroll
            for (int q = 0; q < 4; q++) acc[i][j][q] = 0.f;

    stage_loads(sbase,         mtile, 0, tid);
    stage_loads(sbase + STAGE, mtile, 1, tid);

    for (int c = 0; c < NCHUNK; c++) {
        if (c == NCHUNK - 1) asm volatile("cp.async.wait_group 0;" ::: "memory");
        else                 asm volatile("cp.async.wait_group 1;" ::: "memory");
        __syncthreads();
        if (c + 2 < NCHUNK)
            stage_loads(sbase + ((c + 2) % 3) * STAGE, mtile, c + 2, tid);

        const uint32_t st  = sbase + (uint32_t)(c % 3) * STAGE;
        const uint32_t sAh = st + ahSel;
        const uint32_t sAl = sAh + 8192;
        const uint32_t sBh = st + 32768;
        const uint32_t sBl = st + 40960;

        #pragma unroll
        for (int ks = 0; ks < 2; ks++) {
            uint32_t bh[8], bl[8];
            ldm4(bh[0], bh[1], bh[2], bh[3], sBh + sw64(bOffB + ks * 32));
            ldm4(bh[4], bh[5], bh[6], bh[7], sBh + sw64(bOffB + 1024 + ks * 32));
            ldm4(bl[0], bl[1], bl[2], bl[3], sBl + sw64(bOffB + ks * 32));
            ldm4(bl[4], bl[5], bl[6], bl[7], sBl + sw64(bOffB + 1024 + ks * 32));
            #pragma unroll
            for (int mf = 0; mf < 4; mf++) {
                const uint32_t ao = sw64(aOffB + mf * 1024 + ks * 32);
                uint32_t ah[4], al[4];
                ldm4(ah[0], ah[1], ah[2], ah[3], sAh + ao);
                ldm4(al[0], al[1], al[2], al[3], sAl + ao);
                #pragma unroll
                for (int nf = 0; nf < 4; nf++) {
                    mma_bf16(acc[mf][nf], ah, bh[2 * nf], bh[2 * nf + 1]);
                    mma_bf16(acc[mf][nf], ah, bl[2 * nf], bl[2 * nf + 1]);
                    mma_bf16(acc[mf][nf], al, bh[2 * nf], bh[2 * nf + 1]);
                }
            }
        }
    }

    // ---- epilogue: bias / normalize / relu / store ----
    float bias[4][2];
    #pragma unroll
    for (int nf = 0; nf < 4; nf++) {
        const int col = w_n * 32 + nf * 8 + 2 * tig;
        bias[nf][0] = (col < 96) ? __ldg(b_a + col)     : __ldg(b_b + col - 96);
        bias[nf][1] = (col < 96) ? __ldg(b_a + col + 1) : __ldg(b_b + col - 95);
    }

    #pragma unroll
    for (int mf = 0; mf < 4; mf++) {
        #pragma unroll
        for (int half = 0; half < 2; half++) {
            const int n = (int)mtile + w_m * 64 + mf * 16 + g + half * 8;
            if (n >= N_OUT) continue;
            float inv = 1.f;
            if (w_n == 3) inv = 1.f / fmaxf(__ldg(g_imp + n), 1e-8f);
            #pragma unroll
            for (int nf = 0; nf < 4; nf++) {
                const int col = w_n * 32 + nf * 8 + 2 * tig;
                float2 r;
                r.x = fmaxf(fmaf(acc[mf][nf][half * 2 + 0], inv, bias[nf][0]), 0.f);
                r.y = fmaxf(fmaf(acc[mf][nf][half * 2 + 1], inv, bias[nf][1]), 0.f);
                *reinterpret_cast<float2*>(out + (size_t)n * CO + col) = r;
            }
        }
    }
}

// ---------------------------------------------------------------------------
extern "C" void kernel_launch(void* const* d_in, const int* in_sizes, int n_in,
                              void* d_out, int out_size) {
    const float* feats      = (const float*)d_in[0];
    const float* importance = (const float*)d_in[1];
    const float* W_a        = (const float*)d_in[2];
    const float* b_a        = (const float*)d_in[3];
    const float* W_b        = (const float*)d_in[4];
    const float* b_b        = (const float*)d_in[5];
    const int*   nbr        = (const int*)d_in[6];
    const int*   kid        = (const int*)d_in[7];
    const int*   oid        = (const int*)d_in[8];
    float*       out        = (float*)d_out;

    build_offsets_kernel<<<(NE + 255) / 256, 256>>>(oid);
    pack_edges_kernel<<<(NE + 255) / 256, 256>>>(nbr, kid, importance);
    build_w_kernel<<<(CO * KHALF + 255) / 256, 256>>>(W_a, W_b);
    bin_kernel<<<N_OUT / 8, 256>>>(feats, out);

    const int smem_bytes = 3 * STAGE;   // 147,456 B -> 1 CTA/SM
    cudaFuncSetAttribute(gemm_kernel,
                         cudaFuncAttributeMaxDynamicSharedMemorySize, smem_bytes);
    gemm_kernel<<<NTILES, 256, smem_bytes>>>(b_a, b_b, out);
}

// round 10
// speedup vs baseline: 1.3747x; 1.1781x over previous
#include <cuda_runtime.h>
#include <cuda_bf16.h>
#include <cstdint>

// ---------------- problem constants ----------------
#define N_IN   200000
#define N_OUT  100000
#define NE     1600000
#define CIN    64
#define CO     128
#define KHALF  576
#define MTILE  128
#define MPAD   100096          // 782 * 128
#define NTILES 782
#define KCH    32              // K elems per pipeline chunk
#define NCHUNK 18              // 576 / 32
#define STAGE  49152           // 6 arrays x [128][32] bf16 (8KB each)

#define ASZ    ((size_t)MPAD * KHALF)
#define BSZ    ((size_t)CO * KHALF)

// ---------------- device scratch (no allocs allowed) ----------------
__device__ int            g_offs[N_OUT + 1];
__device__ float          g_imp[N_OUT];
__device__ int2           g_edges[NE];             // {src<<4|k, imp bits}
// A arrays: 0=Auh 1=Aul 2=Awh 3=Awl ; padded rows stay zero (.bss)
__device__ __nv_bfloat16  g_A[4][ASZ];
// B arrays: 0=Bh 1=Bl  (row-major [o][k])
__device__ __nv_bfloat16  g_B[2][BSZ];

// ---------------- helpers ----------------
__device__ __forceinline__ uint32_t smem_u32(const void* p) {
    uint32_t a;
    asm("{ .reg .u64 t; cvta.to.shared.u64 t, %1; cvt.u32.u64 %0, t; }"
        : "=r"(a) : "l"(p));
    return a;
}
__device__ __forceinline__ uint32_t sw64(uint32_t o) {   // 64B-row swizzle
    return o ^ ((o >> 3) & 0x30);
}
__device__ __forceinline__ void cp16(uint32_t dst, const void* src) {
    asm volatile("cp.async.cg.shared.global [%0], [%1], 16;" :: "r"(dst), "l"(src));
}
#define CP_COMMIT asm volatile("cp.async.commit_group;" ::: "memory")

__device__ __forceinline__ void ldm4(uint32_t& r0, uint32_t& r1,
                                     uint32_t& r2, uint32_t& r3, uint32_t a) {
    asm volatile("ldmatrix.sync.aligned.m8n8.x4.shared.b16 {%0,%1,%2,%3}, [%4];"
                 : "=r"(r0), "=r"(r1), "=r"(r2), "=r"(r3) : "r"(a));
}
__device__ __forceinline__ void mma_bf16(float* c, const uint32_t* a,
                                         uint32_t b0, uint32_t b1) {
    asm volatile(
        "mma.sync.aligned.m16n8k16.row.col.f32.bf16.bf16.f32 "
        "{%0,%1,%2,%3}, {%4,%5,%6,%7}, {%8,%9}, {%0,%1,%2,%3};"
        : "+f"(c[0]), "+f"(c[1]), "+f"(c[2]), "+f"(c[3])
        : "r"(a[0]), "r"(a[1]), "r"(a[2]), "r"(a[3]), "r"(b0), "r"(b1));
}

// ---------------------------------------------------------------------------
// Kernel 1: CSR offsets via adjacent-diff over sorted neighbors_out_index
// ---------------------------------------------------------------------------
__global__ void build_offsets_kernel(const int* __restrict__ out_idx) {
    int e = blockIdx.x * blockDim.x + threadIdx.x;
    if (e >= NE) return;
    int b = __ldg(out_idx + e);
    int a = (e == 0) ? -1 : __ldg(out_idx + e - 1);
    for (int n = a + 1; n <= b; n++) g_offs[n] = e;
    if (e == NE - 1)
        for (int n = b + 1; n <= N_OUT; n++) g_offs[n] = NE;
}

// ---------------------------------------------------------------------------
// Kernel 1b: pack per-edge records {src<<4 | k, importance[src]}
// ---------------------------------------------------------------------------
__global__ void pack_edges_kernel(const int* __restrict__ nbr,
                                  const int* __restrict__ kid,
                                  const float* __restrict__ importance) {
    int e = blockIdx.x * blockDim.x + threadIdx.x;
    if (e >= NE) return;
    const int src = __ldg(nbr + e);
    const int k   = __ldg(kid + e);
    int2 r;
    r.x = (src << 4) | k;
    r.y = __float_as_int(__ldg(importance + src));
    g_edges[e] = r;
}

// ---------------------------------------------------------------------------
// Kernel 2: compressed weights [128][576] bf16 hi/lo
// ---------------------------------------------------------------------------
__global__ void build_w_kernel(const float* __restrict__ Wa,
                               const float* __restrict__ Wb) {
    int i = blockIdx.x * blockDim.x + threadIdx.x;
    if (i >= CO * KHALF) return;
    int o = i / KHALF, k = i % KHALF;
    float v = (o < 96) ? __ldg(Wa + k * 96 + o) : __ldg(Wb + k * 32 + (o - 96));
    __nv_bfloat16 h = __float2bfloat16(v);
    g_B[0][i] = h;
    g_B[1][i] = __float2bfloat16(v - __bfloat162float(h));
}

// ---------------------------------------------------------------------------
// Kernel 3: binning. One warp per output point; INTERLEAVED fp32 bins in smem
// (float4 {ux,uy,wx,wy} per (k,lane)) -> 1 LDS.128 + 1 STS.128 per edge.
// ---------------------------------------------------------------------------
__global__ __launch_bounds__(256)
void bin_kernel(const float* __restrict__ feats,
                float*       __restrict__ out) {
    __shared__ float4 sb[8][9 * 32];       // per warp: [k][lane] -> {ux,uy,wx,wy}
    const int lane = threadIdx.x & 31;
    const int w    = threadIdx.x >> 5;
    const int n    = blockIdx.x * 8 + w;

    float4* b4 = sb[w];
    #pragma unroll
    for (int i = lane; i < 9 * 32; i += 32) b4[i] = make_float4(0.f, 0.f, 0.f, 0.f);
    __syncwarp();

    const int e0 = g_offs[n], e1 = g_offs[n + 1];
    float impacc = 0.f;
    #pragma unroll 4
    for (int e = e0; e < e1; e++) {
        const int2  rec = __ldg(g_edges + e);
        const int   src = rec.x >> 4;
        const int   k   = rec.x & 15;
        const float im  = __int_as_float(rec.y);
        const float2 f  = *reinterpret_cast<const float2*>(
                              feats + (size_t)src * CIN + 2 * lane);
        const int o4 = k * 32 + lane;
        float4 v = b4[o4];
        v.x += f.x;
        v.y += f.y;
        v.z = fmaf(f.x, im, v.z);
        v.w = fmaf(f.y, im, v.w);
        b4[o4] = v;
        impacc += im;
    }
    __syncwarp();

    // writeout: lane owns channel pair (2l, 2l+1) for each k.
    const size_t rb = (size_t)n * KHALF;
    #pragma unroll
    for (int k = 0; k < 9; k++) {
        const float4 v = b4[k * 32 + lane];
        const size_t off = rb + k * 64 + 2 * lane;
        __nv_bfloat162 hh, ll;
        // u pair -> arrays 0/1
        hh.x = __float2bfloat16(v.x); hh.y = __float2bfloat16(v.y);
        ll.x = __float2bfloat16(v.x - __bfloat162float(hh.x));
        ll.y = __float2bfloat16(v.y - __bfloat162float(hh.y));
        *reinterpret_cast<uint32_t*>(&g_A[0][off]) = *reinterpret_cast<uint32_t*>(&hh);
        *reinterpret_cast<uint32_t*>(&g_A[1][off]) = *reinterpret_cast<uint32_t*>(&ll);
        // w pair -> arrays 2/3
        hh.x = __float2bfloat16(v.z); hh.y = __float2bfloat16(v.w);
        ll.x = __float2bfloat16(v.z - __bfloat162float(hh.x));
        ll.y = __float2bfloat16(v.w - __bfloat162float(hh.y));
        *reinterpret_cast<uint32_t*>(&g_A[2][off]) = *reinterpret_cast<uint32_t*>(&hh);
        *reinterpret_cast<uint32_t*>(&g_A[3][off]) = *reinterpret_cast<uint32_t*>(&ll);
    }
    if (lane == 0) {
        g_imp[n] = impacc;
        out[(size_t)N_OUT * CO + n] = impacc;   // imp_sum output
    }
}

// ---------------------------------------------------------------------------
// Kernel 4: HMMA GEMM — round-4 config verbatim (measured 151 us):
// 2 stages x 48KB, __launch_bounds__(256,2), B in smem via ldmatrix,
// issue(c+1) before wait_group. Stage: [Auh|Aul|Awh|Awl|Bh|Bl] x 8KB,
// 64B rows, sw64. Warps 2(M64) x 4(N32); w_n<3 -> Au, w_n==3 -> Aw.
// ---------------------------------------------------------------------------
extern __shared__ __align__(128) char gsm[];

__global__ __launch_bounds__(256, 2)
void gemm_kernel(const float* __restrict__ b_a,
                 const float* __restrict__ b_b,
                 float*       __restrict__ out) {
    const int tid = threadIdx.x, lane = tid & 31, wid = tid >> 5;
    const int w_m = wid & 1, w_n = wid >> 1;
    const int g = lane >> 2, tig = lane & 3;
    const size_t mtile = (size_t)blockIdx.x * MTILE;
    const uint32_t sbase = smem_u32(gsm);

    // cp.async geometry: 2 x 16B per thread per array (128 rows x 4 cols)
    int   aIdx[2], bIdx[2];
    uint32_t dOff[2];
    #pragma unroll
    for (int q = 0; q < 2; q++) {
        const int idx = q * 256 + tid;      // 0..511
        const int row = idx >> 2, c = idx & 3;
        aIdx[q] = (int)((mtile + row) * KHALF + c * 8);
        bIdx[q] = row * KHALF + c * 8;
        dOff[q] = sw64(row * 64 + c * 16);
    }

    // ldmatrix per-lane base offsets, 64B rows
    const uint32_t aOffB = (uint32_t)(w_m * 64 + (lane & 15)) * 64
                         + ((lane >> 4) & 1) * 16;
    const uint32_t bOffB = (uint32_t)(w_n * 32 + (lane & 7) + ((lane >> 4) & 1) * 8) * 64
                         + ((lane >> 3) & 1) * 16;
    const uint32_t ahSel = (w_n < 3) ? 0u : 16384u;   // Auh vs Awh

    float acc[4][4][4];
    #pragma unroll
    for (int i = 0; i < 4; i++)
        #pragma unroll
        for (int j = 0; j < 4; j++)
            #pragma unroll
            for (int q = 0; q < 4; q++) acc[i][j][q] = 0.f;

    auto issue = [&](int c) {
        const uint32_t st = sbase + (uint32_t)(c & 1) * STAGE;
        const int k0 = c * KCH;
        #pragma unroll
        for (int q = 0; q < 2; q++) {
            #pragma unroll
            for (int arr = 0; arr < 4; arr++)
                cp16(st + arr * 8192 + dOff[q], &g_A[arr][0] + aIdx[q] + k0);
            #pragma unroll
            for (int arr = 0; arr < 2; arr++)
                cp16(st + 32768 + arr * 8192 + dOff[q], &g_B[arr][0] + bIdx[q] + k0);
        }
        CP_COMMIT;
    };

    issue(0);

    #pragma unroll 2
    for (int c = 0; c < NCHUNK; c++) {
        if (c + 1 < NCHUNK) {
            issue(c + 1);
            asm volatile("cp.async.wait_group 1;" ::: "memory");
        } else {
            asm volatile("cp.async.wait_group 0;" ::: "memory");
        }
        __syncthreads();

        const uint32_t st  = sbase + (uint32_t)(c & 1) * STAGE;
        const uint32_t sAh = st + ahSel;
        const uint32_t sAl = sAh + 8192;
        const uint32_t sBh = st + 32768;
        const uint32_t sBl = st + 40960;

        #pragma unroll
        for (int ks = 0; ks < 2; ks++) {
            uint32_t bh[8], bl[8];
            ldm4(bh[0], bh[1], bh[2], bh[3], sBh + sw64(bOffB + ks * 32));
            ldm4(bh[4], bh[5], bh[6], bh[7], sBh + sw64(bOffB + 1024 + ks * 32));
            ldm4(bl[0], bl[1], bl[2], bl[3], sBl + sw64(bOffB + ks * 32));
            ldm4(bl[4], bl[5], bl[6], bl[7], sBl + sw64(bOffB + 1024 + ks * 32));
            #pragma unroll
            for (int mf = 0; mf < 4; mf++) {
                const uint32_t ao = sw64(aOffB + mf * 1024 + ks * 32);
                uint32_t ah[4], al[4];
                ldm4(ah[0], ah[1], ah[2], ah[3], sAh + ao);
                ldm4(al[0], al[1], al[2], al[3], sAl + ao);
                #pragma unroll
                for (int nf = 0; nf < 4; nf++) {
                    mma_bf16(acc[mf][nf], ah, bh[2 * nf], bh[2 * nf + 1]);
                    mma_bf16(acc[mf][nf], ah, bl[2 * nf], bl[2 * nf + 1]);
                    mma_bf16(acc[mf][nf], al, bh[2 * nf], bh[2 * nf + 1]);
                }
            }
        }
        __syncthreads();
    }

    // ---- epilogue: bias / normalize / relu / store ----
    float bias[4][2];
    #pragma unroll
    for (int nf = 0; nf < 4; nf++) {
        const int col = w_n * 32 + nf * 8 + 2 * tig;
        bias[nf][0] = (col < 96) ? __ldg(b_a + col)     : __ldg(b_b + col - 96);
        bias[nf][1] = (col < 96) ? __ldg(b_a + col + 1) : __ldg(b_b + col - 95);
    }

    #pragma unroll
    for (int mf = 0; mf < 4; mf++) {
        #pragma unroll
        for (int half = 0; half < 2; half++) {
            const int n = (int)mtile + w_m * 64 + mf * 16 + g + half * 8;
            if (n >= N_OUT) continue;
            float inv = 1.f;
            if (w_n == 3) inv = 1.f / fmaxf(__ldg(g_imp + n), 1e-8f);
            #pragma unroll
            for (int nf = 0; nf < 4; nf++) {
                const int col = w_n * 32 + nf * 8 + 2 * tig;
                float2 r;
                r.x = fmaxf(fmaf(acc[mf][nf][half * 2 + 0], inv, bias[nf][0]), 0.f);
                r.y = fmaxf(fmaf(acc[mf][nf][half * 2 + 1], inv, bias[nf][1]), 0.f);
                *reinterpret_cast<float2*>(out + (size_t)n * CO + col) = r;
            }
        }
    }
}

// ---------------------------------------------------------------------------
extern "C" void kernel_launch(void* const* d_in, const int* in_sizes, int n_in,
                              void* d_out, int out_size) {
    const float* feats      = (const float*)d_in[0];
    const float* importance = (const float*)d_in[1];
    const float* W_a        = (const float*)d_in[2];
    const float* b_a        = (const float*)d_in[3];
    const float* W_b        = (const float*)d_in[4];
    const float* b_b        = (const float*)d_in[5];
    const int*   nbr        = (const int*)d_in[6];
    const int*   kid        = (const int*)d_in[7];
    const int*   oid        = (const int*)d_in[8];
    float*       out        = (float*)d_out;

    build_offsets_kernel<<<(NE + 255) / 256, 256>>>(oid);
    pack_edges_kernel<<<(NE + 255) / 256, 256>>>(nbr, kid, importance);
    build_w_kernel<<<(CO * KHALF + 255) / 256, 256>>>(W_a, W_b);
    bin_kernel<<<N_OUT / 8, 256>>>(feats, out);

    const int smem_bytes = 2 * STAGE;   // 98,304 B -> 2 CTAs/SM
    cudaFuncSetAttribute(gemm_kernel,
                         cudaFuncAttributeMaxDynamicSharedMemorySize, smem_bytes);
    gemm_kernel<<<NTILES, 256, smem_bytes>>>(b_a, b_b, out);
}